// round 11
// baseline (speedup 1.0000x reference)
#include <cuda_runtime.h>
#include <cstdint>

// Problem constants (match reference)
#define B      32
#define TMAX   512
#define D      384
#define MAXDUR 8
#define TOUT   (TMAX * (MAXDUR - 1))   // 3584
#define VEC    (D / 4)                 // 96 float4 per row
#define NTHR   128                     // 4 warps
#define ROWS_PER_CTA 4                 // 4 warps, 1 output row each
#define CTAS_PER_B   (TOUT / ROWS_PER_CTA)   // 896
#define NCTAS  (B * CTAS_PER_B)        // 28672

// ---------------------------------------------------------------------------
// Fused kernel, R4 gather path, smaller CTA shape (4 warps / 4 rows per CTA).
// Probes the downward direction of the CTA-shape curve: finer work quanta ->
// better wave/tail balance; scan ALU per row doubles but ALU is non-binding
// (measured R2-R10). Each CTA:
//   1. int4-loads its batch's 512 durations (4/thread), masks by ilen,
//      block-scans into smem cum
//   2. all-zero fallback (cum[t] = min(t+1, L))
//   3. each warp binary-searches its frame (searchsorted right, 10 steps)
//   4. warp gathers 96 float4 of xs[b, idx, :] -> out row (__stcs)
// ---------------------------------------------------------------------------
__global__ void __launch_bounds__(NTHR) lenreg_fused_kernel(
    const float4* __restrict__ xs,     // [B, TMAX, VEC]
    const int4*   __restrict__ ds4,    // [B, TMAX/4]  (ds viewed as int4)
    const int*    __restrict__ ilens,  // [B]
    float4*       __restrict__ out)    // [B, TOUT, VEC]
{
    const int cta    = blockIdx.x;
    const int b      = cta / CTAS_PER_B;              // mul-shift
    const int f_base = (cta - b * CTAS_PER_B) * ROWS_PER_CTA;

    const int t    = threadIdx.x;     // 0..127
    const int lane = t & 31;
    const int wid  = t >> 5;          // 0..3

    __shared__ int s_cum[TMAX];       // inclusive cumsum of masked durations
    __shared__ int s_wsum[4];

    const int L = ilens[b];

    // --- block scan: thread t owns elements 4t..4t+3 (one int4 load) -------
    const int e = 4 * t;
    int4 dd = __ldg(ds4 + b * (TMAX / 4) + t);
    int d0 = (e     < L) ? dd.x : 0;
    int d1 = (e + 1 < L) ? dd.y : 0;
    int d2 = (e + 2 < L) ? dd.z : 0;
    int d3 = (e + 3 < L) ? dd.w : 0;

    const int q01 = d0 + d1;
    const int q   = q01 + d2 + d3;     // thread-local sum of 4

    // warp inclusive scan of 4-sums (covers 128 elements per warp)
    int p = q;
    #pragma unroll
    for (int off = 1; off < 32; off <<= 1) {
        int v = __shfl_up_sync(0xffffffffu, p, off);
        if (lane >= off) p += v;
    }
    if (lane == 31) s_wsum[wid] = p;
    __syncthreads();

    // cross-warp exclusive offset (4 values)
    int woff = 0;
    #pragma unroll
    for (int w = 0; w < 4; ++w)
        woff += (w < wid) ? s_wsum[w] : 0;

    const int excl = p - q + woff;     // exclusive prefix before element e
    s_cum[e]     = excl + d0;
    s_cum[e + 1] = excl + q01;
    s_cum[e + 2] = excl + q01 + d2;
    s_cum[e + 3] = excl + q;
    __syncthreads();

    int total = s_cum[TMAX - 1];
    if (total == 0) {
        // all-zero fallback: d = mask -> cum[t'] = min(t'+1, L)
        s_cum[e]     = (e     < L) ? (e + 1) : L;
        s_cum[e + 1] = (e + 1 < L) ? (e + 2) : L;
        s_cum[e + 2] = (e + 2 < L) ? (e + 3) : L;
        s_cum[e + 3] = (e + 3 < L) ? (e + 4) : L;
        total = L;                         // L >= 1 guaranteed
        __syncthreads();
    }

    // --- per-warp: binary search + gather -----------------------------------
    const int f = f_base + wid;            // this warp's output frame

    // searchsorted(cum, f, side='right'); 10 steps for range [0, 512]
    int lo = 0, hi = TMAX;
    #pragma unroll
    for (int step = 0; step < 10; ++step) {
        int mid = (lo + hi) >> 1;
        if (s_cum[mid] <= f) lo = mid + 1; else hi = mid;
    }
    const int idx = (lo < TMAX - 1) ? lo : (TMAX - 1);

    float4* dst = out + ((long)b * TOUT + f) * VEC;

    if (f < total) {
        const float4* src = xs + ((long)b * TMAX + idx) * VEC;
        float4 r0 = __ldg(src + lane);
        float4 r1 = __ldg(src + lane + 32);
        float4 r2 = __ldg(src + lane + 64);
        __stcs(dst + lane,      r0);
        __stcs(dst + lane + 32, r1);
        __stcs(dst + lane + 64, r2);
    } else {
        const float4 z = make_float4(0.f, 0.f, 0.f, 0.f);
        __stcs(dst + lane,      z);
        __stcs(dst + lane + 32, z);
        __stcs(dst + lane + 64, z);
    }
}

extern "C" void kernel_launch(void* const* d_in, const int* in_sizes, int n_in,
                              void* d_out, int out_size)
{
    const float* xs    = (const float*)d_in[0];  // [B, TMAX, D] fp32
    const int*   ds    = (const int*)  d_in[1];  // [B, TMAX] int32
    const int*   ilens = (const int*)  d_in[2];  // [B] int32
    float*       out   = (float*)d_out;          // [B, TOUT, D] fp32

    lenreg_fused_kernel<<<NCTAS, NTHR>>>(
        (const float4*)xs, (const int4*)ds, ilens, (float4*)out);
}

// round 12
// speedup vs baseline: 1.0011x; 1.0011x over previous
#include <cuda_runtime.h>
#include <cstdint>

// Problem constants (match reference)
#define B      32
#define TMAX   512
#define D      384
#define MAXDUR 8
#define TOUT   (TMAX * (MAXDUR - 1))   // 3584
#define VEC    (D / 4)                 // 96 float4 per row
#define ROWS_PER_CTA 8                 // 8 warps, 1 output row each
#define CTAS_PER_B   (TOUT / ROWS_PER_CTA)   // 448
#define NCTAS  (B * CTAS_PER_B)        // 14336

// ---------------------------------------------------------------------------
// FINAL kernel — best measured configuration (29.15us, reproduced 29.4us).
// Single fused kernel. Each CTA (256 thr = 8 warps):
//   1. loads its batch's 512 durations, masks by ilen, block-scans to smem cum
//   2. all-zero fallback (cum[t] = min(t+1, L))
//   3. each warp binary-searches its output frame f in cum (searchsorted right,
//      10 steps: insertion point range [0,512] needs ceil(log2(513)) = 10)
//   4. warp gathers 96 float4 of xs[b, idx, :] -> out row (streaming stores)
//
// Measured conclusions (R2-R11):
//   - HBM wall: 201 MB mandatory traffic @ ~6.9 TB/s effective (86% of spec).
//   - Issue/ALU utilization 9%-43% does not move the time (non-binding).
//   - CTA shape curve: 4/8 rows per CTA tie at the minimum; 16/32 regress.
//   - __stcs beats __stwt (+5.3us) and smem staging + cp.async.bulk (+5.9us).
// ---------------------------------------------------------------------------
__global__ void __launch_bounds__(256) lenreg_fused_kernel(
    const float4* __restrict__ xs,     // [B, TMAX, VEC]
    const int*    __restrict__ ds,     // [B, TMAX]
    const int*    __restrict__ ilens,  // [B]
    float4*       __restrict__ out)    // [B, TOUT, VEC]
{
    const int cta    = blockIdx.x;
    const int b      = cta / CTAS_PER_B;              // mul-shift
    const int f_base = (cta - b * CTAS_PER_B) * ROWS_PER_CTA;

    const int t    = threadIdx.x;     // 0..255
    const int lane = t & 31;
    const int wid  = t >> 5;          // 0..7

    __shared__ int s_cum[TMAX];       // inclusive cumsum of masked durations
    __shared__ int s_wsum[8];

    const int L = ilens[b];

    // --- block scan: thread t owns elements 2t, 2t+1 --------------------
    const int e0 = 2 * t;
    const int e1 = 2 * t + 1;
    int d0 = (e0 < L) ? __ldg(ds + b * TMAX + e0) : 0;
    int d1 = (e1 < L) ? __ldg(ds + b * TMAX + e1) : 0;
    int pair = d0 + d1;

    // warp inclusive scan of pair sums
    int p = pair;
    #pragma unroll
    for (int off = 1; off < 32; off <<= 1) {
        int v = __shfl_up_sync(0xffffffffu, p, off);
        if (lane >= off) p += v;
    }
    if (lane == 31) s_wsum[wid] = p;
    __syncthreads();

    // cross-warp exclusive offset (8 values, scanned redundantly per thread)
    int woff = 0;
    #pragma unroll
    for (int w = 0; w < 8; ++w)
        woff += (w < wid) ? s_wsum[w] : 0;

    const int excl = p - pair + woff;     // exclusive prefix before e0
    s_cum[e0] = excl + d0;
    s_cum[e1] = excl + d0 + d1;
    __syncthreads();

    int total = s_cum[TMAX - 1];

    if (total == 0) {
        // all-zero fallback: d = mask -> cum[t'] = min(t'+1, L)
        s_cum[e0] = (e0 < L) ? (e0 + 1) : L;
        s_cum[e1] = (e1 < L) ? (e1 + 1) : L;
        total = L;                         // L >= 1 guaranteed
        __syncthreads();
    }

    // --- per-warp: binary search + gather --------------------------------
    const int f = f_base + wid;            // this warp's output frame

    // searchsorted(cum, f, side='right'): first idx with cum[idx] > f.
    // 10 iterations to fully collapse [0, 512] insertion range.
    int lo = 0, hi = TMAX;
    #pragma unroll
    for (int step = 0; step < 10; ++step) {
        int mid = (lo + hi) >> 1;
        if (s_cum[mid] <= f) lo = mid + 1; else hi = mid;
    }
    int idx = (lo < TMAX - 1) ? lo : (TMAX - 1);

    float4* dst = out + ((long)b * TOUT + f) * VEC;

    if (f < total) {
        const float4* src = xs + ((long)b * TMAX + idx) * VEC;
        float4 r0 = __ldg(src + lane);
        float4 r1 = __ldg(src + lane + 32);
        float4 r2 = __ldg(src + lane + 64);
        __stcs(dst + lane,      r0);
        __stcs(dst + lane + 32, r1);
        __stcs(dst + lane + 64, r2);
    } else {
        const float4 z = make_float4(0.f, 0.f, 0.f, 0.f);
        __stcs(dst + lane,      z);
        __stcs(dst + lane + 32, z);
        __stcs(dst + lane + 64, z);
    }
}

extern "C" void kernel_launch(void* const* d_in, const int* in_sizes, int n_in,
                              void* d_out, int out_size)
{
    const float* xs    = (const float*)d_in[0];  // [B, TMAX, D] fp32
    const int*   ds    = (const int*)  d_in[1];  // [B, TMAX] int32
    const int*   ilens = (const int*)  d_in[2];  // [B] int32
    float*       out   = (float*)d_out;          // [B, TOUT, D] fp32

    lenreg_fused_kernel<<<NCTAS, 256>>>(
        (const float4*)xs, ds, ilens, (float4*)out);
}